// round 14
// baseline (speedup 1.0000x reference)
#include <cuda_runtime.h>
#include <math.h>
#include <stdint.h>

#define BB 8
#define AA 64
#define DE 128
#define MM 512
#define DH 64
#define ZD 128

#define MG 16          // m-groups (partials per (b,a))
#define MPG 32         // m per CTA
#define NBUF 4         // pipeline buffers (1 m = 32KB each)

__device__ float g_dH2[BB * MM];
__device__ float g_logv[BB * MM * DH];
// partial states per (b,a,mg)
__device__ float g_pm[BB * AA * MG * 2];
__device__ float g_pe[BB * AA * MG * DE];
__device__ float g_pv[BB * AA * MG * DH];

__device__ __forceinline__ float warp_sum(float v) {
#pragma unroll
    for (int o = 16; o > 0; o >>= 1) v += __shfl_xor_sync(0xffffffffu, v, o);
    return v;
}

__device__ __forceinline__ void cp16(unsigned int dst, const void* src) {
    asm volatile("cp.async.cg.shared.global [%0], [%1], 16;\n" :: "r"(dst), "l"(src));
}
__device__ __forceinline__ void cp_commit() {
    asm volatile("cp.async.commit_group;\n" ::: "memory");
}
__device__ __forceinline__ void cp_wait2() {
    asm volatile("cp.async.wait_group 2;\n" ::: "memory");
}

// ---------------------------------------------------------------------------
// Prologue: per (b,m) Poincare dH2 + log-map vector. One warp per (b,m).
// ---------------------------------------------------------------------------
__global__ void __launch_bounds__(256) prologue_kernel(
    const float* __restrict__ currH,   // [B, DH]
    const float* __restrict__ demoH)   // [B*M, DH]
{
    int gw = blockIdx.x * 8 + (threadIdx.x >> 5);
    int l = threadIdx.x & 31;
    if (gw >= BB * MM) return;
    int b = gw >> 9;

    float x0 = currH[b * DH + 2 * l], x1 = currH[b * DH + 2 * l + 1];
    float y0 = demoH[(size_t)gw * DH + 2 * l], y1 = demoH[(size_t)gw * DH + 2 * l + 1];

    const float thr = 1.0f - 1e-5f;
    float x2 = warp_sum(x0 * x0 + x1 * x1);
    float nx = fmaxf(sqrtf(x2), 1e-15f);
    if (nx > thr) { float s = thr / nx; x0 *= s; x1 *= s; x2 *= s * s; }
    float y2 = warp_sum(y0 * y0 + y1 * y1);
    float ny = fmaxf(sqrtf(y2), 1e-15f);
    if (ny > thr) { float s = thr / ny; y0 *= s; y1 *= s; y2 *= s * s; }

    float xy = warp_sum(x0 * y0 + x1 * y1);

    float Ac = 1.0f - 2.0f * xy + y2;
    float Bc = 1.0f - x2;
    float den = fmaxf(1.0f - 2.0f * xy + x2 * y2, 1e-15f);
    float inv = 1.0f / den;
    float u0 = (Bc * y0 - Ac * x0) * inv;
    float u1 = (Bc * y1 - Ac * x1) * inv;

    float un2 = warp_sum(u0 * u0 + u1 * u1);
    float un = fmaxf(sqrtf(un2), 1e-15f);
    float arg = fminf(un, 1.0f - 1e-7f);
    float at = atanhf(arg);

    if (l == 0) g_dH2[gw] = 4.0f * at * at;

    float sc = fmaxf(1.0f - x2, 1e-15f) * at / un;
    g_logv[(size_t)gw * DH + 2 * l]     = sc * u0;
    g_logv[(size_t)gw * DH + 2 * l + 1] = sc * u1;
}

// ---------------------------------------------------------------------------
// Main: grid 128 = (b, mg). 1024 threads / 32 warps; warp w owns a = 2w, 2w+1.
// Streams the CONTIGUOUS 1MB slab demo[b, m0..m0+31, :, :] via a 4-deep
// cp.async pipeline (32KB per stage = one full [A,de] block). Per-warp
// online softmax states for its two a's live in registers; unnormalized
// partials written to scratch at the end.
// ---------------------------------------------------------------------------
__global__ void __launch_bounds__(1024, 1) main_kernel(
    const float* __restrict__ curr_rho,  // [B, A, DE]
    const float* __restrict__ demo_rho)  // [B, M, A, DE]
{
    const int bi = blockIdx.x;            // b*MG + mg
    const int b = bi >> 4, mg = bi & 15;
    const int mbase = mg * MPG;
    const int tid = threadIdx.x;
    const int w = tid >> 5, l = tid & 31;
    const int a0 = 2 * w, a1 = 2 * w + 1;

    extern __shared__ float smem[];
    float* sd  = smem;                      // NBUF * 8192 floats (4 x 32KB)
    float* sl  = smem + NBUF * AA * DE;     // NBUF * 64 floats
    float* sh2 = sl + NBUF * DH;            // 32 floats

    if (tid < MPG) sh2[tid] = g_dH2[b * MM + mbase + tid];

    const float* dsrc = demo_rho + (size_t)(b * MM + mbase) * AA * DE;  // + m*8192
    const float* lsrc = g_logv + (size_t)(b * MM + mbase) * DH;
    unsigned int sdb0 = (unsigned int)__cvta_generic_to_shared(sd);
    unsigned int slb0 = (unsigned int)__cvta_generic_to_shared(sl);

    // issue stages 0..2 (stage = one m = 32KB; 2 cp16 per thread)
#pragma unroll
    for (int q = 0; q < 3; q++) {
        unsigned int bo = (unsigned int)(q & (NBUF - 1));
        cp16(sdb0 + bo * 32768u + tid * 16u, dsrc + (size_t)q * 8192 + tid * 4);
        cp16(sdb0 + bo * 32768u + 16384u + tid * 16u, dsrc + (size_t)q * 8192 + 4096 + tid * 4);
        if (tid < 16) cp16(slb0 + bo * 256u + tid * 16u, lsrc + (size_t)q * 64 + tid * 4);
        cp_commit();
    }

    // current vectors for this warp's two a's (lane owns cols 4l..4l+3)
    const float4 cur0 = reinterpret_cast<const float4*>(curr_rho)[(size_t)(b * AA + a0) * (DE / 4) + l];
    const float4 cur1 = reinterpret_cast<const float4*>(curr_rho)[(size_t)(b * AA + a1) * (DE / 4) + l];

    float mx0 = -3.0e38f, sm0 = 0.f, mx1 = -3.0e38f, sm1 = 0.f;
    float4 ae0 = make_float4(0.f, 0.f, 0.f, 0.f);
    float4 ae1 = make_float4(0.f, 0.f, 0.f, 0.f);
    float2 av0 = make_float2(0.f, 0.f);
    float2 av1 = make_float2(0.f, 0.f);

    for (int k = 0; k < MPG; k++) {
        cp_wait2();
        __syncthreads();
        const int bo = k & (NBUF - 1);
        const float* sdb = sd + bo * (AA * DE);

        float4 dv0 = *reinterpret_cast<const float4*>(sdb + a0 * DE + 4 * l);
        float4 dv1 = *reinterpret_cast<const float4*>(sdb + a1 * DE + 4 * l);
        float2 lv  = *reinterpret_cast<const float2*>(sl + bo * DH + 2 * l);
        float h2 = sh2[k];

        // ---- a0 ----
        {
            float d0 = cur0.x - dv0.x, d1 = cur0.y - dv0.y;
            float d2 = cur0.z - dv0.z, d3 = cur0.w - dv0.w;
            float part = (d0 * d0 + d1 * d1) + (d2 * d2 + d3 * d3);
            part += __shfl_xor_sync(0xffffffffu, part, 1);
            part += __shfl_xor_sync(0xffffffffu, part, 2);
            part += __shfl_xor_sync(0xffffffffu, part, 4);
            part += __shfl_xor_sync(0xffffffffu, part, 8);
            part += __shfl_xor_sync(0xffffffffu, part, 16);
            float s = -(part + h2);                 // warp-uniform
            if (s > mx0) {                          // warp-uniform branch
                float c = __expf(mx0 - s);
                mx0 = s; sm0 *= c;
                ae0.x *= c; ae0.y *= c; ae0.z *= c; ae0.w *= c;
                av0.x *= c; av0.y *= c;
            }
            float p = __expf(s - mx0);
            sm0 += p;
            ae0.x += p * dv0.x; ae0.y += p * dv0.y;
            ae0.z += p * dv0.z; ae0.w += p * dv0.w;
            av0.x += p * lv.x;  av0.y += p * lv.y;
        }
        // ---- a1 ----
        {
            float d0 = cur1.x - dv1.x, d1 = cur1.y - dv1.y;
            float d2 = cur1.z - dv1.z, d3 = cur1.w - dv1.w;
            float part = (d0 * d0 + d1 * d1) + (d2 * d2 + d3 * d3);
            part += __shfl_xor_sync(0xffffffffu, part, 1);
            part += __shfl_xor_sync(0xffffffffu, part, 2);
            part += __shfl_xor_sync(0xffffffffu, part, 4);
            part += __shfl_xor_sync(0xffffffffu, part, 8);
            part += __shfl_xor_sync(0xffffffffu, part, 16);
            float s = -(part + h2);
            if (s > mx1) {
                float c = __expf(mx1 - s);
                mx1 = s; sm1 *= c;
                ae1.x *= c; ae1.y *= c; ae1.z *= c; ae1.w *= c;
                av1.x *= c; av1.y *= c;
            }
            float p = __expf(s - mx1);
            sm1 += p;
            ae1.x += p * dv1.x; ae1.y += p * dv1.y;
            ae1.z += p * dv1.z; ae1.w += p * dv1.w;
            av1.x += p * lv.x;  av1.y += p * lv.y;
        }

        // issue stage k+3 into buffer (k+3)&3 == (k-1)&3 (reads done, sync'd)
        if (k + 3 < MPG) {
            unsigned int bo2 = (unsigned int)((k + 3) & (NBUF - 1));
            cp16(sdb0 + bo2 * 32768u + tid * 16u, dsrc + (size_t)(k + 3) * 8192 + tid * 4);
            cp16(sdb0 + bo2 * 32768u + 16384u + tid * 16u, dsrc + (size_t)(k + 3) * 8192 + 4096 + tid * 4);
            if (tid < 16) cp16(slb0 + bo2 * 256u + tid * 16u, lsrc + (size_t)(k + 3) * 64 + tid * 4);
        }
        cp_commit();   // uniform group count
    }

    // write unnormalized partials straight from registers (coalesced)
    const int p0 = (b * AA + a0) * MG + mg;
    const int p1 = (b * AA + a1) * MG + mg;
    reinterpret_cast<float4*>(g_pe)[(size_t)p0 * (DE / 4) + l] = ae0;
    reinterpret_cast<float4*>(g_pe)[(size_t)p1 * (DE / 4) + l] = ae1;
    reinterpret_cast<float2*>(g_pv)[(size_t)p0 * (DH / 2) + l] = av0;
    reinterpret_cast<float2*>(g_pv)[(size_t)p1 * (DH / 2) + l] = av1;
    if (l == 0) {
        g_pm[p0 * 2 + 0] = mx0; g_pm[p0 * 2 + 1] = sm0;
        g_pm[p1 * 2 + 0] = mx1; g_pm[p1 * 2 + 1] = sm1;
    }
}

// ---------------------------------------------------------------------------
// Merge: 512 CTAs x 128 threads. Merge 16 partials per (b,a), then
// exp-map + GEMVs + LayerNorm.
// ---------------------------------------------------------------------------
__global__ void __launch_bounds__(128) merge_kernel(
    const float* __restrict__ currH,     // [B, DH]
    const float* __restrict__ We,        // [64, DE]
    const float* __restrict__ Wh,        // [64, DH]
    const float* __restrict__ gamma,     // [ZD]
    const float* __restrict__ beta,      // [ZD]
    float* __restrict__ out)             // [B, A, ZD]
{
    const int bx = blockIdx.x;
    const int b = bx >> 6;
    const int tid = threadIdx.x;
    const int w = tid >> 5, l = tid & 31;

    __shared__ float s_eout[DE];
    __shared__ float s_v[DH];
    __shared__ float s_h[DH];
    __shared__ float s_red[8];

    float mxq[MG], smq[MG];
#pragma unroll
    for (int q = 0; q < MG; q++) {
        mxq[q] = g_pm[(bx * MG + q) * 2 + 0];
        smq[q] = g_pm[(bx * MG + q) * 2 + 1];
    }
    float gm = -3.0e38f;
#pragma unroll
    for (int q = 0; q < MG; q++) gm = fmaxf(gm, mxq[q]);
    float S = 0.f;
#pragma unroll
    for (int q = 0; q < MG; q++) { mxq[q] = __expf(mxq[q] - gm); S += mxq[q] * smq[q]; }
    float invS = 1.0f / S;

    {
        float e = 0.f;
#pragma unroll
        for (int q = 0; q < MG; q++) e += mxq[q] * g_pe[(size_t)(bx * MG + q) * DE + tid];
        s_eout[tid] = e * invS;
    }
    if (tid < DH) {
        float v = 0.f;
#pragma unroll
        for (int q = 0; q < MG; q++) v += mxq[q] * g_pv[(size_t)(bx * MG + q) * DH + tid];
        s_v[tid] = v * invS;
    }
    __syncthreads();

    // exp-map on warp 0 (lane l owns dims 2l, 2l+1)
    if (w == 0) {
        float x0 = currH[b * DH + 2 * l], x1 = currH[b * DH + 2 * l + 1];
        const float thr = 1.0f - 1e-5f;
        float x2 = warp_sum(x0 * x0 + x1 * x1);
        float nx = fmaxf(sqrtf(x2), 1e-15f);
        if (nx > thr) { float s0 = thr / nx; x0 *= s0; x1 *= s0; x2 *= s0 * s0; }
        float lam = 2.0f / fmaxf(1.0f - x2, 1e-15f);

        float v0 = s_v[2 * l], v1 = s_v[2 * l + 1];
        float vn2 = warp_sum(v0 * v0 + v1 * v1);
        float vn = fmaxf(sqrtf(vn2), 1e-15f);
        float fac = tanhf(lam * vn * 0.5f);
        float iv = fac / vn;
        float y0 = v0 * iv, y1 = v1 * iv;

        float yn2 = warp_sum(y0 * y0 + y1 * y1);
        float yn = fmaxf(sqrtf(yn2), 1e-15f);
        if (yn > thr) { float s0 = thr / yn; y0 *= s0; y1 *= s0; yn2 *= s0 * s0; }

        float xy = warp_sum(x0 * y0 + x1 * y1);
        float den = fmaxf(1.0f + 2.0f * xy + x2 * yn2, 1e-15f);
        float ca = (1.0f + 2.0f * xy + yn2) / den;
        float cb2 = (1.0f - x2) / den;
        float o0 = ca * x0 + cb2 * y0, o1 = ca * x1 + cb2 * y1;

        float on2 = warp_sum(o0 * o0 + o1 * o1);
        float on = fmaxf(sqrtf(on2), 1e-15f);
        if (on > thr) { float s0 = thr / on; o0 *= s0; o1 *= s0; }
        s_h[2 * l] = o0; s_h[2 * l + 1] = o1;
    }
    __syncthreads();

    // GEMVs + LayerNorm
    float zj;
    if (tid < 64) {
        const float* wr = We + tid * DE;
        float acc = 0.f;
#pragma unroll 8
        for (int d = 0; d < DE; d++) acc += wr[d] * s_eout[d];
        zj = acc;
    } else {
        const float* wr = Wh + (tid - 64) * DH;
        float acc = 0.f;
#pragma unroll 8
        for (int d = 0; d < DH; d++) acc += wr[d] * s_h[d];
        zj = acc;
    }
    float p1 = warp_sum(zj);
    float p2 = warp_sum(zj * zj);
    if (l == 0) { s_red[w] = p1; s_red[4 + w] = p2; }
    __syncthreads();
    float sum = s_red[0] + s_red[1] + s_red[2] + s_red[3];
    float sq  = s_red[4] + s_red[5] + s_red[6] + s_red[7];
    float mean = sum * (1.0f / ZD);
    float var = sq * (1.0f / ZD) - mean * mean;
    float r = rsqrtf(var + 1e-5f);
    out[(size_t)bx * ZD + tid] = (zj - mean) * r * gamma[tid] + beta[tid];
}

extern "C" void kernel_launch(void* const* d_in, const int* in_sizes, int n_in,
                              void* d_out, int out_size) {
    const float* curr_rho = (const float*)d_in[0];
    const float* currH    = (const float*)d_in[1];
    const float* demo_rho = (const float*)d_in[2];
    const float* demoH    = (const float*)d_in[3];
    const float* We       = (const float*)d_in[4];
    const float* Wh       = (const float*)d_in[5];
    const float* gamma    = (const float*)d_in[6];
    const float* beta     = (const float*)d_in[7];
    float* out = (float*)d_out;

    const int smem_bytes = (NBUF * AA * DE + NBUF * DH + MPG) * 4;  // ~132 KB
    cudaFuncSetAttribute(main_kernel, cudaFuncAttributeMaxDynamicSharedMemorySize, smem_bytes);

    prologue_kernel<<<512, 256>>>(currH, demoH);
    main_kernel<<<BB * MG, 1024, smem_bytes>>>(curr_rho, demo_rho);
    merge_kernel<<<BB * AA, 128>>>(currH, We, Wh, gamma, beta, out);
}